// round 10
// baseline (speedup 1.0000x reference)
#include <cuda_runtime.h>
#include <cuda_bf16.h>
#include <cstdint>

// ---------------- problem constants ----------------
#define NT 131072     // tokens
#define DM 2048       // d_model
#define DH 256        // d_hid
#define NH 16         // heads
#define WMAX 64       // window

// ---------------- scratch (device globals; no allocs allowed) ----------------
__device__ __nv_bfloat16 g_w1bT[(size_t)DH * DM];  // [n][k] bf16
__device__ __nv_bfloat16 g_qvbh[32 * DH];          // hi: [j][k], j<16 -> q[j], j>=16 -> v[j-16]
__device__ __nv_bfloat16 g_qvbl[32 * DH];          // lo residual
__device__ float g_logitsT[(size_t)NH * NT];       // [h][token]
__device__ float g_valsT[(size_t)NH * NT];         // [h][token]
__device__ unsigned int g_headmax[NH];             // order-preserving float keys

// ---------------- helpers ----------------
__device__ __forceinline__ uint32_t smem_u32(const void* p) {
    uint32_t a;
    asm("{ .reg .u64 t; cvta.to.shared.u64 t, %1; cvt.u32.u64 %0, t; }" : "=r"(a) : "l"(p));
    return a;
}

#define SWZ128(off) ((off) ^ (((off) >> 3) & 0x70))   // 128B-row tiles
#define SWZ512(off) ((off) ^ (((off) >> 5) & 0x70))   // 512B-row tiles

__device__ __forceinline__ void ldmx4(uint32_t* r, uint32_t addr) {
    asm volatile("ldmatrix.sync.aligned.m8n8.x4.shared.b16 {%0,%1,%2,%3}, [%4];"
        : "=r"(r[0]), "=r"(r[1]), "=r"(r[2]), "=r"(r[3]) : "r"(addr));
}
__device__ __forceinline__ void mma16816(float* d, const uint32_t* a, uint32_t b0, uint32_t b1) {
    asm volatile("mma.sync.aligned.m16n8k16.row.col.f32.bf16.bf16.f32 "
        "{%0,%1,%2,%3},{%4,%5,%6,%7},{%8,%9},{%0,%1,%2,%3};"
        : "+f"(d[0]), "+f"(d[1]), "+f"(d[2]), "+f"(d[3])
        : "r"(a[0]), "r"(a[1]), "r"(a[2]), "r"(a[3]), "r"(b0), "r"(b1));
}
__device__ __forceinline__ void cpasync16(uint32_t dst, const void* src) {
    asm volatile("cp.async.cg.shared.global [%0], [%1], 16;" :: "r"(dst), "l"(src) : "memory");
}
__device__ __forceinline__ float4 ldcs4(const float* p) {
    float4 v;
    asm volatile("ld.global.cs.v4.f32 {%0,%1,%2,%3}, [%4];"
        : "=f"(v.x), "=f"(v.y), "=f"(v.z), "=f"(v.w) : "l"(p));
    return v;
}

// ---------------- GEMM config ----------------
#define TM 128
#define TN 256
#define KC 64
#define NCH (DM / KC)   // 32 chunks
#define NSTG 3
#define ASTG (TM * KC * 2)   // 16384
#define BSTG (TN * KC * 2)   // 32768

// SMEM layout (bytes) — mainloop stages
#define SM_A   0                        // 3 * 16384 = 49152
#define SM_B   (NSTG * ASTG)            // 49152 .. 49152+98304 = 147456
// epilogue overlays (stage buffers dead by then)
#define SM_YH  0                        // 128 x 256 bf16, 512B rows = 65536
#define SM_YL  65536                    // 65536
#define SM_QH  131072                   // 32 x 256 bf16 = 16384
#define SM_QL  147456                   // 16384
#define SM_B1  163840                   // 1KB bias
#define SMEM_SZ 164864

extern "C" __global__ void __launch_bounds__(512, 1)
gemm_probe_kernel(const float* __restrict__ x, const float* __restrict__ b1)
{
    extern __shared__ char smem[];
    const uint32_t sb = smem_u32(smem);
    const int tid = threadIdx.x;
    const int wid = tid >> 5, lid = tid & 31;
    const long row0 = (long)blockIdx.x * TM;

    if (tid < DH) ((float*)(smem + SM_B1))[tid] = b1[tid];

    // per-thread load mappings (4 pieces each for A and B)
    const float* aP[4]; uint32_t aOff[4];
    const char*  bP[4]; uint32_t bOff[4];
    #pragma unroll
    for (int i = 0; i < 4; i++) {
        const int u = tid + i * 512;
        const int r = u >> 4, cg = u & 15;            // A: 128 rows x 16 float4
        aP[i] = x + row0 * (long)DM + r * DM + cg * 4;
        aOff[i] = SWZ128((uint32_t)(r * 128 + cg * 8));
        const int n = u >> 3, g = u & 7;              // B: 256 rows x 8 int4
        bP[i] = (const char*)g_w1bT + (long)n * (DM * 2) + g * 16;
        bOff[i] = SWZ128((uint32_t)(n * 128 + g * 16));
    }

    float4 af[4];
    // ---- prologue ----
    {   // B chunk 0
        const uint32_t bb = sb + SM_B;
        #pragma unroll
        for (int i = 0; i < 4; i++) cpasync16(bb + bOff[i], bP[i]);
        asm volatile("cp.async.commit_group;" ::: "memory");
    }
    #pragma unroll
    for (int i = 0; i < 4; i++) af[i] = ldcs4(aP[i]);   // A chunk 0
    {   // STS A0
        char* ab = smem + SM_A;
        #pragma unroll
        for (int i = 0; i < 4; i++) {
            __nv_bfloat162 p0 = __float22bfloat162_rn(make_float2(af[i].x, af[i].y));
            __nv_bfloat162 p1 = __float22bfloat162_rn(make_float2(af[i].z, af[i].w));
            uint2 wv;
            wv.x = *reinterpret_cast<uint32_t*>(&p0);
            wv.y = *reinterpret_cast<uint32_t*>(&p1);
            *(uint2*)(ab + aOff[i]) = wv;
        }
    }
    {   // B chunk 1
        const uint32_t bb = sb + SM_B + BSTG;
        #pragma unroll
        for (int i = 0; i < 4; i++) cpasync16(bb + bOff[i], bP[i] + KC * 2);
        asm volatile("cp.async.commit_group;" ::: "memory");
    }
    #pragma unroll
    for (int i = 0; i < 4; i++) af[i] = ldcs4(aP[i] + KC);  // A chunk 1

    const int mw = wid & 3, nw = wid >> 2;              // 4x4 warp grid, 32x64 tiles
    const int lrow = lid & 15, lkb = (lid >> 4) * 16;   // ldmatrix lane mapping
    float acc[2][8][4];
    #pragma unroll
    for (int m = 0; m < 2; m++)
        #pragma unroll
        for (int t = 0; t < 8; t++)
            #pragma unroll
            for (int e = 0; e < 4; e++) acc[m][t][e] = 0.f;

    // ---- mainloop ----
    #pragma unroll 1
    for (int ch = 0; ch < NCH; ch++) {
        asm volatile("cp.async.wait_group 1;" ::: "memory");
        __syncthreads();
        const int s1 = (ch + 1) % NSTG, s2 = (ch + 2) % NSTG;
        if (ch + 1 < NCH) {                     // STS A(ch+1) from regs
            char* ab = smem + SM_A + s1 * ASTG;
            #pragma unroll
            for (int i = 0; i < 4; i++) {
                __nv_bfloat162 p0 = __float22bfloat162_rn(make_float2(af[i].x, af[i].y));
                __nv_bfloat162 p1 = __float22bfloat162_rn(make_float2(af[i].z, af[i].w));
                uint2 wv;
                wv.x = *reinterpret_cast<uint32_t*>(&p0);
                wv.y = *reinterpret_cast<uint32_t*>(&p1);
                *(uint2*)(ab + aOff[i]) = wv;
            }
        }
        if (ch + 2 < NCH) {                     // prefetch chunk ch+2
            const int k0 = (ch + 2) * KC;
            #pragma unroll
            for (int i = 0; i < 4; i++) af[i] = ldcs4(aP[i] + k0);
            const uint32_t bb = sb + SM_B + s2 * BSTG;
            #pragma unroll
            for (int i = 0; i < 4; i++) cpasync16(bb + bOff[i], bP[i] + k0 * 2);
        }
        asm volatile("cp.async.commit_group;" ::: "memory");

        // compute chunk ch
        const uint32_t aB = sb + SM_A + (ch % NSTG) * ASTG;
        const uint32_t bB = sb + SM_B + (ch % NSTG) * BSTG;
        #pragma unroll
        for (int ks = 0; ks < 4; ks++) {
            uint32_t a[2][4], b[4][4];
            #pragma unroll
            for (int mt = 0; mt < 2; mt++)
                ldmx4(a[mt], aB + SWZ128((uint32_t)((mw * 32 + mt * 16 + lrow) * 128 + ks * 32 + lkb)));
            #pragma unroll
            for (int nt = 0; nt < 4; nt++)
                ldmx4(b[nt], bB + SWZ128((uint32_t)((nw * 64 + nt * 16 + lrow) * 128 + ks * 32 + lkb)));
            #pragma unroll
            for (int mt = 0; mt < 2; mt++)
                #pragma unroll
                for (int nt = 0; nt < 4; nt++) {
                    mma16816(acc[mt][2 * nt],     a[mt], b[nt][0], b[nt][2]);
                    mma16816(acc[mt][2 * nt + 1], a[mt], b[nt][1], b[nt][3]);
                }
        }
    }
    __syncthreads();   // mainloop done; stage smem is dead

    // ---- epilogue A: bias+relu, y -> SMEM as split bf16 (hi+lo), 512B rows ----
    {
        const float* b1s = (const float*)(smem + SM_B1);
        char* yh = smem + SM_YH;
        char* yl = smem + SM_YL;
        const int g4 = lid >> 2, t4 = lid & 3;
        #pragma unroll
        for (int mt = 0; mt < 2; mt++)
            #pragma unroll
            for (int t = 0; t < 8; t++) {
                const int r = mw * 32 + mt * 16 + g4;
                const int c = nw * 64 + t * 8 + t4 * 2;
                const float bc0 = b1s[c], bc1 = b1s[c + 1];
                const float v00 = fmaxf(acc[mt][t][0] + bc0, 0.f);
                const float v01 = fmaxf(acc[mt][t][1] + bc1, 0.f);
                const float v10 = fmaxf(acc[mt][t][2] + bc0, 0.f);
                const float v11 = fmaxf(acc[mt][t][3] + bc1, 0.f);
                __nv_bfloat162 h0 = __float22bfloat162_rn(make_float2(v00, v01));
                __nv_bfloat162 h1 = __float22bfloat162_rn(make_float2(v10, v11));
                __nv_bfloat162 l0 = __float22bfloat162_rn(make_float2(
                    v00 - __bfloat162float(h0.x), v01 - __bfloat162float(h0.y)));
                __nv_bfloat162 l1 = __float22bfloat162_rn(make_float2(
                    v10 - __bfloat162float(h1.x), v11 - __bfloat162float(h1.y)));
                const uint32_t o0 = SWZ512((uint32_t)(r * 512 + c * 2));
                const uint32_t o1 = SWZ512((uint32_t)((r + 8) * 512 + c * 2));
                *(uint32_t*)(yh + o0) = *reinterpret_cast<uint32_t*>(&h0);
                *(uint32_t*)(yh + o1) = *reinterpret_cast<uint32_t*>(&h1);
                *(uint32_t*)(yl + o0) = *reinterpret_cast<uint32_t*>(&l0);
                *(uint32_t*)(yl + o1) = *reinterpret_cast<uint32_t*>(&l1);
            }
        // stage QV hi/lo (32 x 256 bf16 each) into SMEM, same row layout
        #pragma unroll
        for (int i = 0; i < 2; i++) {
            const int u = tid + i * 512;             // 1024 int4 per table
            const uint32_t off = (uint32_t)((u >> 5) * 512 + (u & 31) * 16);
            *(int4*)(smem + SM_QH + SWZ512(off)) = *(const int4*)((const char*)g_qvbh + off);
            *(int4*)(smem + SM_QL + SWZ512(off)) = *(const int4*)((const char*)g_qvbl + off);
        }
    }
    __syncthreads();

    // ---- epilogue B: [logits|vals](128x32) = Y(128x256) @ QV^T, split-bf16, 3 passes ----
    {
        const int wr = wid & 7;        // row group (16 rows)
        const int wn = wid >> 3;       // 0 -> logits heads, 1 -> vals heads
        float d[2][4];
        #pragma unroll
        for (int i = 0; i < 2; i++)
            #pragma unroll
            for (int e = 0; e < 4; e++) d[i][e] = 0.f;
        const uint32_t yhB = sb + SM_YH, ylB = sb + SM_YL;
        const uint32_t qhB = sb + SM_QH, qlB = sb + SM_QL;
        #pragma unroll
        for (int ks = 0; ks < 16; ks++) {
            const uint32_t yOff = SWZ512((uint32_t)((wr * 16 + lrow) * 512 + ks * 32 + lkb));
            const uint32_t qOff = SWZ512((uint32_t)((wn * 16 + lrow) * 512 + ks * 32 + lkb));
            uint32_t ah[4], al[4], bh[4], bl[4];
            ldmx4(ah, yhB + yOff);
            ldmx4(bh, qhB + qOff);
            ldmx4(bl, qlB + qOff);
            ldmx4(al, ylB + yOff);
            mma16816(d[0], ah, bh[0], bh[2]);
            mma16816(d[1], ah, bh[1], bh[3]);
            mma16816(d[0], ah, bl[0], bl[2]);
            mma16816(d[1], ah, bl[1], bl[3]);
            mma16816(d[0], al, bh[0], bh[2]);
            mma16816(d[1], al, bh[1], bh[3]);
        }
        float* const base = wn ? g_valsT : g_logitsT;
        const long r0 = row0 + wr * 16 + (lid >> 2);
        #pragma unroll
        for (int nt = 0; nt < 2; nt++) {
            const int j = nt * 8 + (lid & 3) * 2;   // head pair within table
            base[(long)j * NT + r0]            = d[nt][0];
            base[(long)(j + 1) * NT + r0]      = d[nt][1];
            base[(long)j * NT + r0 + 8]        = d[nt][2];
            base[(long)(j + 1) * NT + r0 + 8]  = d[nt][3];
        }
    }
}

// ---------------- prep kernels ----------------
__global__ void prep_w1_kernel(const float* __restrict__ w1) {
    __shared__ float tile[32][33];
    const int nb = blockIdx.x * 32, kb = blockIdx.y * 32;
    for (int r = threadIdx.y; r < 32; r += 8)
        tile[r][threadIdx.x] = w1[(long)(kb + r) * DH + nb + threadIdx.x];
    __syncthreads();
    for (int r = threadIdx.y; r < 32; r += 8)
        g_w1bT[(long)(nb + r) * DM + kb + threadIdx.x] = __float2bfloat16(tile[threadIdx.x][r]);
}

__global__ void prep_qv_kernel(const float* __restrict__ q, const float* __restrict__ v) {
    const int i = blockIdx.x * 256 + threadIdx.x;   // 8192 elements
    const int j = i >> 8, k = i & 255;
    const float val = (j < 16) ? q[j * DH + k] : v[(j - 16) * DH + k];
    const __nv_bfloat16 h = __float2bfloat16(val);
    g_qvbh[j * DH + k] = h;
    g_qvbl[j * DH + k] = __float2bfloat16(val - __bfloat162float(h));
    if (blockIdx.x == 0 && threadIdx.x < NH) g_headmax[threadIdx.x] = 0u;
}

// ---------------- windowed softmax-mean + max ----------------
__device__ __forceinline__ unsigned f2key(float f) {
    unsigned u = __float_as_uint(f);
    return (u & 0x80000000u) ? ~u : (u | 0x80000000u);
}
__device__ __forceinline__ float key2f(unsigned k) {
    unsigned u = (k & 0x80000000u) ? (k & 0x7FFFFFFFu) : ~k;
    return __uint_as_float(u);
}

#define SPAN 2048
__global__ void __launch_bounds__(256, 4)
window_kernel(const int* __restrict__ wsz)
{
    __shared__ float2 buf[1 + SPAN + WMAX];   // prefix sums of (e, e*v)
    __shared__ float2 tot[256];
    __shared__ float  wmax[8];

    const int h = blockIdx.y;
    const long base = (long)blockIdx.x * SPAN;
    const int t = threadIdx.x;
    int w = wsz ? wsz[0] : WMAX;
    if (w > WMAX) w = WMAX;
    if (w < 1) w = 1;
    const int load = (int)min((long)(SPAN + w - 1), (long)NT - base);

    const float* lg = g_logitsT + (long)h * NT + base;
    const float* vl = g_valsT   + (long)h * NT + base;

    if (t == 0) buf[0] = make_float2(0.f, 0.f);
    for (int i = t; i < load; i += 256) {
        const float e = expf(lg[i]);
        buf[1 + i] = make_float2(e, e * vl[i]);
    }
    __syncthreads();

    const int s0 = 1 + t * 9;
    const int s1 = min(s0 + 9, 1 + load);
    float2 run = make_float2(0.f, 0.f);
    for (int i = s0; i < s1; i++) { run.x += buf[i].x; run.y += buf[i].y; buf[i] = run; }
    tot[t] = run;
    __syncthreads();
    for (int off = 1; off < 256; off <<= 1) {
        float2 add = make_float2(0.f, 0.f);
        if (t >= off) add = tot[t - off];
        __syncthreads();
        tot[t].x += add.x; tot[t].y += add.y;
        __syncthreads();
    }
    float2 offv = (t > 0) ? tot[t - 1] : make_float2(0.f, 0.f);
    for (int i = s0; i < s1; i++) { buf[i].x += offv.x; buf[i].y += offv.y; }
    __syncthreads();

    float best = -3.402823466e38f;
    for (int a = t; a < SPAN; a += 256) {
        if (a + w <= load) {
            const float2 hi = buf[a + w];
            const float2 lo = buf[a];
            best = fmaxf(best, (hi.y - lo.y) / (hi.x - lo.x));
        }
    }
    #pragma unroll
    for (int o = 16; o; o >>= 1) best = fmaxf(best, __shfl_xor_sync(0xFFFFFFFFu, best, o));
    if ((t & 31) == 0) wmax[t >> 5] = best;
    __syncthreads();
    if (t == 0) {
        float m = wmax[0];
        #pragma unroll
        for (int i = 1; i < 8; i++) m = fmaxf(m, wmax[i]);
        atomicMax(&g_headmax[h], f2key(m));
    }
}

__global__ void final_kernel(float* __restrict__ out) {
    if (threadIdx.x == 0) {
        float s = 0.f;
        #pragma unroll
        for (int hh = 0; hh < NH; hh++) s += key2f(g_headmax[hh]);
        out[0] = s;
    }
}

// ---------------- launch ----------------
extern "C" void kernel_launch(void* const* d_in, const int* in_sizes, int n_in,
                              void* d_out, int out_size)
{
    const float* x  = (const float*)d_in[0];
    const float* w1 = (const float*)d_in[1];
    const float* b1 = (const float*)d_in[2];
    const float* q  = (const float*)d_in[3];
    const float* v  = (const float*)d_in[4];
    const int* wsz  = (n_in > 5) ? (const int*)d_in[5] : nullptr;

    cudaFuncSetAttribute(gemm_probe_kernel, cudaFuncAttributeMaxDynamicSharedMemorySize, SMEM_SZ);

    prep_w1_kernel<<<dim3(DH / 32, DM / 32), dim3(32, 8)>>>(w1);
    prep_qv_kernel<<<32, 256>>>(q, v);
    gemm_probe_kernel<<<NT / TM, 512, SMEM_SZ>>>(x, b1);
    window_kernel<<<dim3(NT / SPAN, NH), 256>>>(wsz);
    final_kernel<<<1, 32>>>((float*)d_out);
}